// round 11
// baseline (speedup 1.0000x reference)
#include <cuda_runtime.h>
#include <cuda_fp16.h>
#include <cstdint>

#define NCTX 4096
#define DMODEL 2048

// ---------------- scratch (static device globals; no runtime alloc) ----------------
__device__ float g_s[(size_t)NCTX * NCTX];                        // 64 MB approx scores
__device__ __align__(256) __half g_xh[(size_t)NCTX * DMODEL];
__device__ __align__(256) __half g_xl[(size_t)NCTX * DMODEL];
__device__ __align__(256) __half g_wqh[(size_t)DMODEL * DMODEL];
__device__ __align__(256) __half g_wql[(size_t)DMODEL * DMODEL];
__device__ __align__(256) __half g_wvh[(size_t)DMODEL * DMODEL];
__device__ __align__(256) __half g_qh[(size_t)NCTX * DMODEL];
__device__ __align__(256) __half g_ql[(size_t)NCTX * DMODEL];
__device__ __align__(256) __half g_zh[(size_t)NCTX * DMODEL];

// ---------------- GEMM config ----------------
// 128x128 CTA tile, 128 threads (4 warps in 2x2 grid), warp tile 64x64, BK=32.
constexpr int BM = 128, BN = 128, BK = 32;
constexpr int TILE_B = BM * BK * 2;                 // 8192 B per matrix tile
constexpr int NSTAGE = 3;

__device__ __forceinline__ uint32_t sm_addr(const void* p) {
    uint32_t a;
    asm("{ .reg .u64 t; cvta.to.shared.u64 t, %1; cvt.u32.u64 %0, t; }" : "=r"(a) : "l"(p));
    return a;
}
__device__ __forceinline__ void cpasync16(uint32_t s, const void* g) {
    asm volatile("cp.async.cg.shared.global [%0], [%1], 16;" :: "r"(s), "l"(g));
}
__device__ __forceinline__ void ldmx4(uint32_t& r0, uint32_t& r1, uint32_t& r2, uint32_t& r3,
                                      uint32_t a) {
    asm volatile("ldmatrix.sync.aligned.m8n8.x4.shared.b16 {%0,%1,%2,%3}, [%4];"
                 : "=r"(r0), "=r"(r1), "=r"(r2), "=r"(r3) : "r"(a));
}
__device__ __forceinline__ void mma16816(float* c, const uint32_t* a, const uint32_t* b) {
    asm volatile("mma.sync.aligned.m16n8k16.row.col.f32.f16.f16.f32 "
                 "{%0,%1,%2,%3}, {%4,%5,%6,%7}, {%8,%9}, {%0,%1,%2,%3};"
                 : "+f"(c[0]), "+f"(c[1]), "+f"(c[2]), "+f"(c[3])
                 : "r"(a[0]), "r"(a[1]), "r"(a[2]), "r"(a[3]), "r"(b[0]), "r"(b[1]));
}
__device__ __forceinline__ uint32_t swoff(int row, int j) {
    return row * 64 + ((j ^ ((row >> 1) & 3)) << 4);
}

// ---------------- split-precision fp16 NT GEMM via mma.sync ----------------
// NPASS==3: hh+hl+lh.  NPASS==1: hh only.
// CSKIP: skip strictly-upper causal blocks.
// 2 CTAs/SM, 4 warps/CTA, warp tile 64x64 (LDSM/MMA ratio 1.5x better than 64x32).
template<int NPASS, bool SPLIT_OUT, bool CSKIP>
__global__ __launch_bounds__(128, 2)
void tgemm(const __half* __restrict__ Ah, const __half* __restrict__ Al,
           const __half* __restrict__ Bh, const __half* __restrict__ Bl,
           float* __restrict__ Cf, __half* __restrict__ Ch, __half* __restrict__ Cl,
           int K, int lda, int ldb, int ldc)
{
    const int bx = blockIdx.x, by = blockIdx.y;
    if (CSKIP && bx > by) return;
    const int nC = K / BK;

    constexpr int NMAT = (NPASS == 3) ? 4 : 2;      // Ah,[Al],Bh,[Bl... ] slots
    constexpr int STAGE_ = NMAT * TILE_B;
    // slot order: Ah, (Al), Bh, (Bl) — Bh offset depends on NPASS
    constexpr int OFF_AL = TILE_B;
    constexpr int OFF_BH = (NPASS == 3) ? 2 * TILE_B : TILE_B;
    constexpr int OFF_BL = 3 * TILE_B;              // only used when NPASS==3

    extern __shared__ __align__(1024) char smem[];
    const uint32_t sb = sm_addr(smem);

    const int tid = threadIdx.x;                    // 0..127
    const int lane = tid & 31, wid = tid >> 5;      // 4 warps
    const int wm = wid & 1, wn = wid >> 1;          // 2x2 warp grid

    const int lrow = tid >> 1;                      // 0..63
    const int pr   = tid & 1;                       // chunk pair select
    const size_t arow = (size_t)(by * BM + lrow) * lda;
    const size_t brow = (size_t)(bx * BN + lrow) * ldb;

    float acc[4][8][4];
    #pragma unroll
    for (int i = 0; i < 4; i++)
        #pragma unroll
        for (int j = 0; j < 8; j++)
            #pragma unroll
            for (int r = 0; r < 4; r++) acc[i][j][r] = 0.f;

    auto issue = [&](int c) {
        const uint32_t s0 = sb + (c % NSTAGE) * STAGE_;
        const int kc = c * BK;
        #pragma unroll
        for (int r = 0; r < 2; r++) {               // rows lrow and lrow+64
            const int row = lrow + r * 64;
            const size_t ga = arow + (size_t)r * 64 * lda + kc;
            const size_t gb = brow + (size_t)r * 64 * ldb + kc;
            #pragma unroll
            for (int jj = 0; jj < 2; jj++) {
                const int j = 2 * pr + jj;
                const uint32_t so = swoff(row, j);
                cpasync16(s0 + so, Ah + ga + j * 8);
                if (NPASS == 3) cpasync16(s0 + OFF_AL + so, Al + ga + j * 8);
                cpasync16(s0 + OFF_BH + so, Bh + gb + j * 8);
                if (NPASS == 3) cpasync16(s0 + OFF_BL + so, Bl + gb + j * 8);
            }
        }
    };

    issue(0); asm volatile("cp.async.commit_group;");
    issue(1); asm volatile("cp.async.commit_group;");

    for (int c = 0; c < nC; c++) {
        asm volatile("cp.async.wait_group 1;");
        __syncthreads();
        if (c + 2 < nC) issue(c + 2);
        asm volatile("cp.async.commit_group;");

        const uint32_t s0 = sb + (c % NSTAGE) * STAGE_;
        #pragma unroll
        for (int ks = 0; ks < 2; ks++) {
            uint32_t a[4][4], b_h[8][2], b_l[8][2];
            // A hi fragments: i = 0..3, rows wm*64 + i*16
            #pragma unroll
            for (int i = 0; i < 4; i++) {
                const int row = wm * 64 + i * 16 + (lane & 15);
                const int ch  = 2 * ks + (lane >> 4);
                ldmx4(a[i][0], a[i][1], a[i][2], a[i][3], s0 + swoff(row, ch));
            }
            // B fragments: p = 0..3 ldmx4 -> frags 2p, 2p+1 (cols wn*64 + ...)
            #pragma unroll
            for (int p = 0; p < 4; p++) {
                const int row = wn * 64 + p * 16 + (lane & 7) + ((lane & 16) >> 1);
                const int ch  = 2 * ks + ((lane >> 3) & 1);
                const uint32_t off = swoff(row, ch);
                uint32_t r0, r1, r2, r3;
                ldmx4(r0, r1, r2, r3, s0 + OFF_BH + off);
                b_h[2 * p][0] = r0; b_h[2 * p][1] = r1;
                b_h[2 * p + 1][0] = r2; b_h[2 * p + 1][1] = r3;
                if (NPASS == 3) {
                    ldmx4(r0, r1, r2, r3, s0 + OFF_BL + off);
                    b_l[2 * p][0] = r0; b_l[2 * p][1] = r1;
                    b_l[2 * p + 1][0] = r2; b_l[2 * p + 1][1] = r3;
                }
            }
            // hh sweep
            #pragma unroll
            for (int i = 0; i < 4; i++)
                #pragma unroll
                for (int j = 0; j < 8; j++)
                    mma16816(acc[i][j], a[i], b_h[j]);
            if (NPASS == 3) {
                // hl sweep
                #pragma unroll
                for (int i = 0; i < 4; i++)
                    #pragma unroll
                    for (int j = 0; j < 8; j++)
                        mma16816(acc[i][j], a[i], b_l[j]);
                // reload a with lo, lh sweep
                #pragma unroll
                for (int i = 0; i < 4; i++) {
                    const int row = wm * 64 + i * 16 + (lane & 15);
                    const int ch  = 2 * ks + (lane >> 4);
                    ldmx4(a[i][0], a[i][1], a[i][2], a[i][3],
                          s0 + OFF_AL + swoff(row, ch));
                }
                #pragma unroll
                for (int i = 0; i < 4; i++)
                    #pragma unroll
                    for (int j = 0; j < 8; j++)
                        mma16816(acc[i][j], a[i], b_h[j]);
            }
        }
    }

    const int r0 = by * BM + wm * 64 + (lane >> 2);
    const int c0 = bx * BN + wn * 64 + (lane & 3) * 2;
    #pragma unroll
    for (int i = 0; i < 4; i++)
        #pragma unroll
        for (int j = 0; j < 8; j++) {
            const int rr = r0 + i * 16;
            const int cc = c0 + j * 8;
            #pragma unroll
            for (int h = 0; h < 2; h++) {
                const float v0 = acc[i][j][2 * h], v1 = acc[i][j][2 * h + 1];
                const size_t o = (size_t)(rr + 8 * h) * ldc + cc;
                if (!SPLIT_OUT) {
                    *(float2*)(Cf + o) = make_float2(v0, v1);
                } else {
                    __half h0 = __float2half_rn(v0), h1 = __float2half_rn(v1);
                    __half l0 = __float2half_rn(v0 - __half2float(h0));
                    __half l1 = __float2half_rn(v1 - __half2float(h1));
                    *(__half2*)(Ch + o) = __halves2half2(h0, h1);
                    *(__half2*)(Cl + o) = __halves2half2(l0, l1);
                }
            }
        }
}

constexpr int SMEM3 = NSTAGE * 4 * TILE_B;   // 96 KB (3-pass)
constexpr int SMEM1 = NSTAGE * 2 * TILE_B;   // 48 KB (1-pass)

// ---------------- fp32 -> fp16 hi/lo split ----------------
__global__ __launch_bounds__(256)
void splitk(const float* __restrict__ in, __half* __restrict__ h, __half* __restrict__ l, int n)
{
    int i = (blockIdx.x * 256 + threadIdx.x) * 4;
    if (i >= n) return;
    float4 v = *(const float4*)(in + i);
    __half h0 = __float2half_rn(v.x), h1 = __float2half_rn(v.y);
    __half h2 = __float2half_rn(v.z), h3 = __float2half_rn(v.w);
    *(__half2*)(h + i)     = __halves2half2(h0, h1);
    *(__half2*)(h + i + 2) = __halves2half2(h2, h3);
    if (l) {
        __half l0 = __float2half_rn(v.x - __half2float(h0));
        __half l1 = __float2half_rn(v.y - __half2float(h1));
        __half l2 = __float2half_rn(v.z - __half2float(h2));
        __half l3 = __float2half_rn(v.w - __half2float(h3));
        *(__half2*)(l + i)     = __halves2half2(l0, l1);
        *(__half2*)(l + i + 2) = __halves2half2(l2, l3);
    }
}

// ---------------- reductions ----------------
__device__ __forceinline__ float warpMax(float v) {
    #pragma unroll
    for (int o = 16; o; o >>= 1) v = fmaxf(v, __shfl_xor_sync(0xffffffffu, v, o));
    return v;
}
__device__ __forceinline__ float warpSum(float v) {
    #pragma unroll
    for (int o = 16; o; o >>= 1) v += __shfl_xor_sync(0xffffffffu, v, o);
    return v;
}

// ---------------- fused screening softmax + exact rescore + AV ----------------
__global__ __launch_bounds__(256)
void softmax_av_fused(const float* __restrict__ S, const __half* __restrict__ Qh,
                      const __half* __restrict__ Ql, const float* __restrict__ x,
                      __half* __restrict__ Zh, int N)
{
    const int row = blockIdx.x;
    const int len = row + 1;
    const float* Srow = S + (size_t)row * N;
    const int tid = threadIdx.x;
    const int lane = tid & 31, wid = tid >> 5;

    __shared__ float red[8];
    __shared__ int scnt;
    __shared__ uint32_t cidx[NCTX];     // 16 KB
    __shared__ float    csc[NCTX];      // 16 KB
    __shared__ float    qs[DMODEL];     // 8 KB
    if (tid == 0) scnt = 0;

    // A: approx row max
    float m = -3.4e38f;
    for (int j = tid; j < len; j += 256) m = fmaxf(m, Srow[j]);
    m = warpMax(m);
    if (lane == 0) red[wid] = m;
    __syncthreads();
    float ma = red[0];
    #pragma unroll
    for (int w = 1; w < 8; w++) ma = fmaxf(ma, red[w]);
    __syncthreads();

    // B: collect candidates; approximate tail mass (relative to ma)
    const float thr = ma - 18.6f;
    float tail = 0.f;
    for (int j = tid; j < len; j += 256) {
        const float v = Srow[j];
        if (v > thr) {
            const int slot = atomicAdd(&scnt, 1);
            cidx[slot] = j;
        } else {
            tail += __expf(v - ma);
        }
    }
    tail = warpSum(tail);
    if (lane == 0) red[wid] = tail;
    // C: q row into smem (fp32 = qh + ql)
    const __half* qhr = Qh + (size_t)row * DMODEL;
    const __half* qlr = Ql + (size_t)row * DMODEL;
    __syncthreads();
    float tsum = 0.f;
    #pragma unroll
    for (int w = 0; w < 8; w++) tsum += red[w];
    for (int k = tid; k < DMODEL; k += 256)
        qs[k] = __half2float(qhr[k]) + __half2float(qlr[k]);
    __syncthreads();

    // D: exact rescoring, one warp per candidate
    const int nc = scnt;
    for (int c = wid; c < nc; c += 8) {
        const float* xr = x + (size_t)cidx[c] * DMODEL;
        float p = 0.f;
        #pragma unroll 4
        for (int k = lane; k < DMODEL; k += 32) p = fmaf(qs[k], xr[k], p);
        p = warpSum(p);
        if (lane == 0) csc[c] = p;
    }
    __syncthreads();

    // E: exact max over candidates
    float mx = -3.4e38f;
    for (int c = tid; c < nc; c += 256) mx = fmaxf(mx, csc[c]);
    mx = warpMax(mx);
    if (lane == 0) red[wid] = mx;
    __syncthreads();
    float me = red[0];
    #pragma unroll
    for (int w = 1; w < 8; w++) me = fmaxf(me, red[w]);
    __syncthreads();

    // F: Z = exact candidate mass + rescaled approximate tail
    float zs = 0.f;
    for (int c = tid; c < nc; c += 256) zs += __expf(csc[c] - me);
    zs = warpSum(zs);
    if (lane == 0) red[wid] = zs;
    __syncthreads();
    float Z = tsum * __expf(ma - me);
    #pragma unroll
    for (int w = 0; w < 8; w++) Z += red[w];
    const float inv = 1.0f / Z;

    // G: weights into csc
    for (int c = tid; c < nc; c += 256) csc[c] = __expf(csc[c] - me) * inv;
    __syncthreads();

    // H: z = sum_j w_j * x_j   (each thread owns 8 dims)
    float acc[8];
    #pragma unroll
    for (int r = 0; r < 8; r++) acc[r] = 0.f;
    const int d0 = tid * 8;
    for (int c = 0; c < nc; c++) {
        const float w = csc[c];
        const float* xr = x + (size_t)cidx[c] * DMODEL + d0;
        const float4 a = *(const float4*)xr;
        const float4 b = *(const float4*)(xr + 4);
        acc[0] = fmaf(w, a.x, acc[0]); acc[1] = fmaf(w, a.y, acc[1]);
        acc[2] = fmaf(w, a.z, acc[2]); acc[3] = fmaf(w, a.w, acc[3]);
        acc[4] = fmaf(w, b.x, acc[4]); acc[5] = fmaf(w, b.y, acc[5]);
        acc[6] = fmaf(w, b.z, acc[6]); acc[7] = fmaf(w, b.w, acc[7]);
    }

    __half* zh = Zh + (size_t)row * DMODEL + d0;
    #pragma unroll
    for (int r = 0; r < 8; r += 2)
        *(__half2*)(zh + r) = __halves2half2(__float2half_rn(acc[r]),
                                             __float2half_rn(acc[r + 1]));
}

// ---------------- host ----------------
extern "C" void kernel_launch(void* const* d_in, const int* in_sizes, int n_in,
                              void* d_out, int out_size)
{
    const float* x   = (const float*)d_in[0];
    const float* Wqk = (const float*)d_in[1];
    const float* Wov = (const float*)d_in[2];
    float* out = (float*)d_out;

    float* s;  cudaGetSymbolAddress((void**)&s, g_s);
    __half *xh, *xl, *wqh, *wql, *wvh, *qh, *ql, *zh;
    cudaGetSymbolAddress((void**)&xh,  g_xh);  cudaGetSymbolAddress((void**)&xl,  g_xl);
    cudaGetSymbolAddress((void**)&wqh, g_wqh); cudaGetSymbolAddress((void**)&wql, g_wql);
    cudaGetSymbolAddress((void**)&wvh, g_wvh);
    cudaGetSymbolAddress((void**)&qh,  g_qh);  cudaGetSymbolAddress((void**)&ql,  g_ql);
    cudaGetSymbolAddress((void**)&zh,  g_zh);

    cudaFuncSetAttribute(tgemm<3, true,  false>, cudaFuncAttributeMaxDynamicSharedMemorySize, SMEM3);
    cudaFuncSetAttribute(tgemm<1, false, true >, cudaFuncAttributeMaxDynamicSharedMemorySize, SMEM1);
    cudaFuncSetAttribute(tgemm<1, false, false>, cudaFuncAttributeMaxDynamicSharedMemorySize, SMEM1);

    const int nx = NCTX * DMODEL, nw = DMODEL * DMODEL;

    splitk<<<nx / 1024, 256>>>(x,   xh,  xl,  nx);
    splitk<<<nw / 1024, 256>>>(Wqk, wqh, wql, nw);
    splitk<<<nw / 1024, 256>>>(Wov, wvh, nullptr, nw);

    // 1) q = x @ Wqk^T -> q hi/lo (3-pass; feeds exact rescoring)
    tgemm<3, true, false><<<dim3(DMODEL / BN, NCTX / BM), 128, SMEM3>>>(
        xh, xl, wqh, wql, nullptr, qh, ql, DMODEL, DMODEL, DMODEL, DMODEL);

    // 2) s~ = qh @ xh^T (1-pass screening; causal block skip) -> approx scores
    tgemm<1, false, true><<<dim3(NCTX / BN, NCTX / BM), 128, SMEM1>>>(
        qh, nullptr, xh, nullptr, s, nullptr, nullptr, DMODEL, DMODEL, DMODEL, NCTX);

    // 3) fused screening softmax + exact rescore + AV -> z (fp16 hi)
    softmax_av_fused<<<NCTX, 256>>>(s, qh, ql, x, zh, NCTX);

    // 4) out = zh @ Wovh^T (1-pass) -> fp32 output
    tgemm<1, false, false><<<dim3(DMODEL / BN, NCTX / BM), 128, SMEM1>>>(
        zh, nullptr, wvh, nullptr, out, nullptr, nullptr, DMODEL, DMODEL, DMODEL, DMODEL);
}

// round 12
// speedup vs baseline: 1.0473x; 1.0473x over previous
#include <cuda_runtime.h>
#include <cuda_fp16.h>
#include <cstdint>

#define NCTX 4096
#define DMODEL 2048

// ---------------- scratch (static device globals; no runtime alloc) ----------------
__device__ __half g_s[(size_t)NCTX * NCTX];                       // 32 MB approx scores (fp16)
__device__ __align__(256) __half g_xh[(size_t)NCTX * DMODEL];
__device__ __align__(256) __half g_xl[(size_t)NCTX * DMODEL];
__device__ __align__(256) __half g_wqh[(size_t)DMODEL * DMODEL];
__device__ __align__(256) __half g_wql[(size_t)DMODEL * DMODEL];
__device__ __align__(256) __half g_wvh[(size_t)DMODEL * DMODEL];
__device__ __align__(256) __half g_qh[(size_t)NCTX * DMODEL];
__device__ __align__(256) __half g_ql[(size_t)NCTX * DMODEL];
__device__ __align__(256) __half g_zh[(size_t)NCTX * DMODEL];

constexpr int BM = 128, BN = 128, BK = 32;
constexpr int TILE_B = BM * BK * 2;                 // 8192 B per matrix tile
constexpr int NSTAGE = 3;
constexpr int SMEM3 = NSTAGE * 4 * TILE_B;          // 96 KB (3-pass: Ah,Al,Bh,Bl)
constexpr int SMEM1 = NSTAGE * 2 * TILE_B;          // 48 KB (1-pass: Ah,Bh)

__device__ __forceinline__ uint32_t sm_addr(const void* p) {
    uint32_t a;
    asm("{ .reg .u64 t; cvta.to.shared.u64 t, %1; cvt.u32.u64 %0, t; }" : "=r"(a) : "l"(p));
    return a;
}
__device__ __forceinline__ void cpasync16(uint32_t s, const void* g) {
    asm volatile("cp.async.cg.shared.global [%0], [%1], 16;" :: "r"(s), "l"(g));
}
__device__ __forceinline__ void ldmx4(uint32_t& r0, uint32_t& r1, uint32_t& r2, uint32_t& r3,
                                      uint32_t a) {
    asm volatile("ldmatrix.sync.aligned.m8n8.x4.shared.b16 {%0,%1,%2,%3}, [%4];"
                 : "=r"(r0), "=r"(r1), "=r"(r2), "=r"(r3) : "r"(a));
}
__device__ __forceinline__ void mma16816(float* c, const uint32_t* a, const uint32_t* b) {
    asm volatile("mma.sync.aligned.m16n8k16.row.col.f32.f16.f16.f32 "
                 "{%0,%1,%2,%3}, {%4,%5,%6,%7}, {%8,%9}, {%0,%1,%2,%3};"
                 : "+f"(c[0]), "+f"(c[1]), "+f"(c[2]), "+f"(c[3])
                 : "r"(a[0]), "r"(a[1]), "r"(a[2]), "r"(a[3]), "r"(b[0]), "r"(b[1]));
}
__device__ __forceinline__ uint32_t swoff(int row, int j) {
    return row * 64 + ((j ^ ((row >> 1) & 3)) << 4);
}

// ============ 3-pass GEMM (q projection): 128 thr, warp tile 64x64, 2 CTAs/SM ============
// C = (Ah+Al) * (Bh+Bl)^T via hh+hl+lh, split hi/lo fp16 output.
__global__ __launch_bounds__(128, 2)
void tgemm3(const __half* __restrict__ Ah, const __half* __restrict__ Al,
            const __half* __restrict__ Bh, const __half* __restrict__ Bl,
            __half* __restrict__ Ch, __half* __restrict__ Cl,
            int K, int lda, int ldb, int ldc)
{
    const int bx = blockIdx.x, by = blockIdx.y;
    const int nC = K / BK;
    constexpr int STAGE_ = 4 * TILE_B;
    constexpr int OFF_AL = TILE_B, OFF_BH = 2 * TILE_B, OFF_BL = 3 * TILE_B;

    extern __shared__ __align__(1024) char smem[];
    const uint32_t sb = sm_addr(smem);

    const int tid = threadIdx.x;
    const int lane = tid & 31, wid = tid >> 5;
    const int wm = wid & 1, wn = wid >> 1;
    const int lrow = tid >> 1;
    const int pr   = tid & 1;
    const size_t arow = (size_t)(by * BM + lrow) * lda;
    const size_t brow = (size_t)(bx * BN + lrow) * ldb;

    float acc[4][8][4];
    #pragma unroll
    for (int i = 0; i < 4; i++)
        #pragma unroll
        for (int j = 0; j < 8; j++)
            #pragma unroll
            for (int r = 0; r < 4; r++) acc[i][j][r] = 0.f;

    auto issue = [&](int c) {
        const uint32_t s0 = sb + (c % NSTAGE) * STAGE_;
        const int kc = c * BK;
        #pragma unroll
        for (int r = 0; r < 2; r++) {
            const int row = lrow + r * 64;
            const size_t ga = arow + (size_t)r * 64 * lda + kc;
            const size_t gb = brow + (size_t)r * 64 * ldb + kc;
            #pragma unroll
            for (int jj = 0; jj < 2; jj++) {
                const int j = 2 * pr + jj;
                const uint32_t so = swoff(row, j);
                cpasync16(s0 + so,          Ah + ga + j * 8);
                cpasync16(s0 + OFF_AL + so, Al + ga + j * 8);
                cpasync16(s0 + OFF_BH + so, Bh + gb + j * 8);
                cpasync16(s0 + OFF_BL + so, Bl + gb + j * 8);
            }
        }
    };

    issue(0); asm volatile("cp.async.commit_group;");
    issue(1); asm volatile("cp.async.commit_group;");

    for (int c = 0; c < nC; c++) {
        asm volatile("cp.async.wait_group 1;");
        __syncthreads();
        if (c + 2 < nC) issue(c + 2);
        asm volatile("cp.async.commit_group;");

        const uint32_t s0 = sb + (c % NSTAGE) * STAGE_;
        #pragma unroll
        for (int ks = 0; ks < 2; ks++) {
            uint32_t a[4][4], b_h[8][2], b_l[8][2];
            #pragma unroll
            for (int i = 0; i < 4; i++) {
                const int row = wm * 64 + i * 16 + (lane & 15);
                const int ch  = 2 * ks + (lane >> 4);
                ldmx4(a[i][0], a[i][1], a[i][2], a[i][3], s0 + swoff(row, ch));
            }
            #pragma unroll
            for (int p = 0; p < 4; p++) {
                const int row = wn * 64 + p * 16 + (lane & 7) + ((lane & 16) >> 1);
                const int ch  = 2 * ks + ((lane >> 3) & 1);
                const uint32_t off = swoff(row, ch);
                uint32_t r0, r1, r2, r3;
                ldmx4(r0, r1, r2, r3, s0 + OFF_BH + off);
                b_h[2 * p][0] = r0; b_h[2 * p][1] = r1;
                b_h[2 * p + 1][0] = r2; b_h[2 * p + 1][1] = r3;
                ldmx4(r0, r1, r2, r3, s0 + OFF_BL + off);
                b_l[2 * p][0] = r0; b_l[2 * p][1] = r1;
                b_l[2 * p + 1][0] = r2; b_l[2 * p + 1][1] = r3;
            }
            #pragma unroll
            for (int i = 0; i < 4; i++)
                #pragma unroll
                for (int j = 0; j < 8; j++)
                    mma16816(acc[i][j], a[i], b_h[j]);
            #pragma unroll
            for (int i = 0; i < 4; i++)
                #pragma unroll
                for (int j = 0; j < 8; j++)
                    mma16816(acc[i][j], a[i], b_l[j]);
            #pragma unroll
            for (int i = 0; i < 4; i++) {
                const int row = wm * 64 + i * 16 + (lane & 15);
                const int ch  = 2 * ks + (lane >> 4);
                ldmx4(a[i][0], a[i][1], a[i][2], a[i][3], s0 + OFF_AL + swoff(row, ch));
            }
            #pragma unroll
            for (int i = 0; i < 4; i++)
                #pragma unroll
                for (int j = 0; j < 8; j++)
                    mma16816(acc[i][j], a[i], b_h[j]);
        }
    }

    const int r0 = by * BM + wm * 64 + (lane >> 2);
    const int c0 = bx * BN + wn * 64 + (lane & 3) * 2;
    #pragma unroll
    for (int i = 0; i < 4; i++)
        #pragma unroll
        for (int j = 0; j < 8; j++) {
            #pragma unroll
            for (int h = 0; h < 2; h++) {
                const float v0 = acc[i][j][2 * h], v1 = acc[i][j][2 * h + 1];
                const size_t o = (size_t)(r0 + i * 16 + 8 * h) * ldc + c0 + j * 8;
                __half h0 = __float2half_rn(v0), h1 = __float2half_rn(v1);
                __half l0 = __float2half_rn(v0 - __half2float(h0));
                __half l1 = __float2half_rn(v1 - __half2float(h1));
                *(__half2*)(Ch + o) = __halves2half2(h0, h1);
                *(__half2*)(Cl + o) = __halves2half2(l0, l1);
            }
        }
}

// ============ 1-pass GEMM: 256 thr, warp tile 64x32, 2 CTAs/SM ============
// OUTK: 0 = fp32 out, 1 = fp16 out.  CSKIP: skip strictly-upper causal blocks.
template<int OUTK, bool CSKIP>
__global__ __launch_bounds__(256, 2)
void tgemm1(const __half* __restrict__ Ah, const __half* __restrict__ Bh,
            float* __restrict__ Cf, __half* __restrict__ Chf,
            int K, int lda, int ldb, int ldc)
{
    const int bx = blockIdx.x, by = blockIdx.y;
    if (CSKIP && bx > by) return;
    const int nC = K / BK;
    constexpr int STAGE_ = 2 * TILE_B;
    constexpr int OFF_B = TILE_B;

    extern __shared__ __align__(1024) char smem[];
    const uint32_t sb = sm_addr(smem);

    const int tid = threadIdx.x;
    const int lane = tid & 31, wid = tid >> 5;
    const int wm = wid & 1, wn = wid >> 1;

    const int lrow = tid >> 1;
    const int ljb  = (tid & 1) * 2;
    const size_t arow = (size_t)(by * BM + lrow) * lda;
    const size_t brow = (size_t)(bx * BN + lrow) * ldb;

    float acc[4][4][4];
    #pragma unroll
    for (int i = 0; i < 4; i++)
        #pragma unroll
        for (int j = 0; j < 4; j++)
            #pragma unroll
            for (int r = 0; r < 4; r++) acc[i][j][r] = 0.f;

    auto issue = [&](int c) {
        const uint32_t s0 = sb + (c % NSTAGE) * STAGE_;
        const int kc = c * BK;
        #pragma unroll
        for (int jj = 0; jj < 2; jj++) {
            const int j = ljb + jj;
            const uint32_t so = swoff(lrow, j);
            cpasync16(s0 + so,         Ah + arow + kc + j * 8);
            cpasync16(s0 + OFF_B + so, Bh + brow + kc + j * 8);
        }
    };

    issue(0); asm volatile("cp.async.commit_group;");
    issue(1); asm volatile("cp.async.commit_group;");

    for (int c = 0; c < nC; c++) {
        asm volatile("cp.async.wait_group 1;");
        __syncthreads();
        if (c + 2 < nC) issue(c + 2);
        asm volatile("cp.async.commit_group;");

        const uint32_t s0 = sb + (c % NSTAGE) * STAGE_;
        #pragma unroll
        for (int ks = 0; ks < 2; ks++) {
            uint32_t a[4][4], b_h[4][2];
            #pragma unroll
            for (int i = 0; i < 4; i++) {
                const int row = wm * 64 + i * 16 + (lane & 15);
                const int ch  = 2 * ks + (lane >> 4);
                ldmx4(a[i][0], a[i][1], a[i][2], a[i][3], s0 + swoff(row, ch));
            }
            #pragma unroll
            for (int p = 0; p < 2; p++) {
                const int row = wn * 32 + p * 16 + (lane & 7) + ((lane & 16) >> 1);
                const int ch  = 2 * ks + ((lane >> 3) & 1);
                uint32_t r0, r1, r2, r3;
                ldmx4(r0, r1, r2, r3, s0 + OFF_B + swoff(row, ch));
                b_h[2 * p][0] = r0; b_h[2 * p][1] = r1;
                b_h[2 * p + 1][0] = r2; b_h[2 * p + 1][1] = r3;
            }
            #pragma unroll
            for (int i = 0; i < 4; i++)
                #pragma unroll
                for (int j = 0; j < 4; j++)
                    mma16816(acc[i][j], a[i], b_h[j]);
        }
    }

    const int r0 = by * BM + wm * 64 + (lane >> 2);
    const int c0 = bx * BN + wn * 32 + (lane & 3) * 2;
    #pragma unroll
    for (int i = 0; i < 4; i++)
        #pragma unroll
        for (int j = 0; j < 4; j++) {
            #pragma unroll
            for (int h = 0; h < 2; h++) {
                const float v0 = acc[i][j][2 * h], v1 = acc[i][j][2 * h + 1];
                const size_t o = (size_t)(r0 + i * 16 + 8 * h) * ldc + c0 + j * 8;
                if (OUTK == 0)
                    *(float2*)(Cf + o) = make_float2(v0, v1);
                else
                    *(__half2*)(Chf + o) = __halves2half2(__float2half_rn(v0),
                                                          __float2half_rn(v1));
            }
        }
}

// ---------------- fp32 -> fp16 hi/lo split ----------------
__global__ __launch_bounds__(256)
void splitk(const float* __restrict__ in, __half* __restrict__ h, __half* __restrict__ l, int n)
{
    int i = (blockIdx.x * 256 + threadIdx.x) * 4;
    if (i >= n) return;
    float4 v = *(const float4*)(in + i);
    __half h0 = __float2half_rn(v.x), h1 = __float2half_rn(v.y);
    __half h2 = __float2half_rn(v.z), h3 = __float2half_rn(v.w);
    *(__half2*)(h + i)     = __halves2half2(h0, h1);
    *(__half2*)(h + i + 2) = __halves2half2(h2, h3);
    if (l) {
        __half l0 = __float2half_rn(v.x - __half2float(h0));
        __half l1 = __float2half_rn(v.y - __half2float(h1));
        __half l2 = __float2half_rn(v.z - __half2float(h2));
        __half l3 = __float2half_rn(v.w - __half2float(h3));
        *(__half2*)(l + i)     = __halves2half2(l0, l1);
        *(__half2*)(l + i + 2) = __halves2half2(l2, l3);
    }
}

// ---------------- reductions ----------------
__device__ __forceinline__ float warpMax(float v) {
    #pragma unroll
    for (int o = 16; o; o >>= 1) v = fmaxf(v, __shfl_xor_sync(0xffffffffu, v, o));
    return v;
}
__device__ __forceinline__ float warpSum(float v) {
    #pragma unroll
    for (int o = 16; o; o >>= 1) v += __shfl_xor_sync(0xffffffffu, v, o);
    return v;
}

// ---------------- fused screening softmax + exact rescore + AV ----------------
// fp16 approx scores; screening margin 18.6 absorbs screening + storage error.
__global__ __launch_bounds__(256)
void softmax_av_fused(const __half* __restrict__ S, const __half* __restrict__ Qh,
                      const __half* __restrict__ Ql, const float* __restrict__ x,
                      __half* __restrict__ Zh, int N)
{
    const int row = blockIdx.x;
    const int len = row + 1;
    const __half* Srow = S + (size_t)row * N;
    const int tid = threadIdx.x;
    const int lane = tid & 31, wid = tid >> 5;

    __shared__ float red[8];
    __shared__ int scnt;
    __shared__ uint32_t cidx[NCTX];
    __shared__ float    csc[NCTX];
    __shared__ float    qs[DMODEL];
    if (tid == 0) scnt = 0;

    // A: approx row max
    float m = -3.4e38f;
    for (int j = tid; j < len; j += 256) m = fmaxf(m, __half2float(Srow[j]));
    m = warpMax(m);
    if (lane == 0) red[wid] = m;
    __syncthreads();
    float ma = red[0];
    #pragma unroll
    for (int w = 1; w < 8; w++) ma = fmaxf(ma, red[w]);
    __syncthreads();

    // B: collect candidates; approximate tail mass
    const float thr = ma - 18.6f;
    float tail = 0.f;
    for (int j = tid; j < len; j += 256) {
        const float v = __half2float(Srow[j]);
        if (v > thr) {
            const int slot = atomicAdd(&scnt, 1);
            cidx[slot] = j;
        } else {
            tail += __expf(v - ma);
        }
    }
    tail = warpSum(tail);
    if (lane == 0) red[wid] = tail;
    // C: q row into smem (fp32 = qh + ql)
    const __half* qhr = Qh + (size_t)row * DMODEL;
    const __half* qlr = Ql + (size_t)row * DMODEL;
    __syncthreads();
    float tsum = 0.f;
    #pragma unroll
    for (int w = 0; w < 8; w++) tsum += red[w];
    for (int k = tid; k < DMODEL; k += 256)
        qs[k] = __half2float(qhr[k]) + __half2float(qlr[k]);
    __syncthreads();

    // D: exact rescoring, one warp per candidate
    const int nc = scnt;
    for (int c = wid; c < nc; c += 8) {
        const float* xr = x + (size_t)cidx[c] * DMODEL;
        float p = 0.f;
        #pragma unroll 4
        for (int k = lane; k < DMODEL; k += 32) p = fmaf(qs[k], xr[k], p);
        p = warpSum(p);
        if (lane == 0) csc[c] = p;
    }
    __syncthreads();

    // E: exact max over candidates
    float mx = -3.4e38f;
    for (int c = tid; c < nc; c += 256) mx = fmaxf(mx, csc[c]);
    mx = warpMax(mx);
    if (lane == 0) red[wid] = mx;
    __syncthreads();
    float me = red[0];
    #pragma unroll
    for (int w = 1; w < 8; w++) me = fmaxf(me, red[w]);
    __syncthreads();

    // F: Z = exact candidate mass + rescaled approximate tail
    float zs = 0.f;
    for (int c = tid; c < nc; c += 256) zs += __expf(csc[c] - me);
    zs = warpSum(zs);
    if (lane == 0) red[wid] = zs;
    __syncthreads();
    float Z = tsum * __expf(ma - me);
    #pragma unroll
    for (int w = 0; w < 8; w++) Z += red[w];
    const float inv = 1.0f / Z;

    // G: weights into csc
    for (int c = tid; c < nc; c += 256) csc[c] = __expf(csc[c] - me) * inv;
    __syncthreads();

    // H: z = sum_j w_j * x_j (each thread owns 8 dims)
    float acc[8];
    #pragma unroll
    for (int r = 0; r < 8; r++) acc[r] = 0.f;
    const int d0 = tid * 8;
    for (int c = 0; c < nc; c++) {
        const float w = csc[c];
        const float* xr = x + (size_t)cidx[c] * DMODEL + d0;
        const float4 a = *(const float4*)xr;
        const float4 b = *(const float4*)(xr + 4);
        acc[0] = fmaf(w, a.x, acc[0]); acc[1] = fmaf(w, a.y, acc[1]);
        acc[2] = fmaf(w, a.z, acc[2]); acc[3] = fmaf(w, a.w, acc[3]);
        acc[4] = fmaf(w, b.x, acc[4]); acc[5] = fmaf(w, b.y, acc[5]);
        acc[6] = fmaf(w, b.z, acc[6]); acc[7] = fmaf(w, b.w, acc[7]);
    }

    __half* zh = Zh + (size_t)row * DMODEL + d0;
    #pragma unroll
    for (int r = 0; r < 8; r += 2)
        *(__half2*)(zh + r) = __halves2half2(__float2half_rn(acc[r]),
                                             __float2half_rn(acc[r + 1]));
}

// ---------------- host ----------------
extern "C" void kernel_launch(void* const* d_in, const int* in_sizes, int n_in,
                              void* d_out, int out_size)
{
    const float* x   = (const float*)d_in[0];
    const float* Wqk = (const float*)d_in[1];
    const float* Wov = (const float*)d_in[2];
    float* out = (float*)d_out;

    __half* s; cudaGetSymbolAddress((void**)&s, g_s);
    __half *xh, *xl, *wqh, *wql, *wvh, *qh, *ql, *zh;
    cudaGetSymbolAddress((void**)&xh,  g_xh);  cudaGetSymbolAddress((void**)&xl,  g_xl);
    cudaGetSymbolAddress((void**)&wqh, g_wqh); cudaGetSymbolAddress((void**)&wql, g_wql);
    cudaGetSymbolAddress((void**)&wvh, g_wvh);
    cudaGetSymbolAddress((void**)&qh,  g_qh);  cudaGetSymbolAddress((void**)&ql,  g_ql);
    cudaGetSymbolAddress((void**)&zh,  g_zh);

    cudaFuncSetAttribute(tgemm3, cudaFuncAttributeMaxDynamicSharedMemorySize, SMEM3);
    cudaFuncSetAttribute(tgemm1<1, true >, cudaFuncAttributeMaxDynamicSharedMemorySize, SMEM1);
    cudaFuncSetAttribute(tgemm1<0, false>, cudaFuncAttributeMaxDynamicSharedMemorySize, SMEM1);

    const int nx = NCTX * DMODEL, nw = DMODEL * DMODEL;

    splitk<<<nx / 1024, 256>>>(x,   xh,  xl,  nx);
    splitk<<<nw / 1024, 256>>>(Wqk, wqh, wql, nw);
    splitk<<<nw / 1024, 256>>>(Wov, wvh, nullptr, nw);

    // 1) q = x @ Wqk^T -> q hi/lo (3-pass, 4-warp 64x64 kernel)
    tgemm3<<<dim3(DMODEL / BN, NCTX / BM), 128, SMEM3>>>(
        xh, xl, wqh, wql, qh, ql, DMODEL, DMODEL, DMODEL, DMODEL);

    // 2) s~ = qh @ xh^T (1-pass screening, causal block skip) -> fp16 scores
    tgemm1<1, true><<<dim3(NCTX / BN, NCTX / BM), 256, SMEM1>>>(
        qh, xh, nullptr, s, DMODEL, DMODEL, DMODEL, NCTX);

    // 3) fused screening softmax + exact rescore + AV -> z (fp16)
    softmax_av_fused<<<NCTX, 256>>>(s, qh, ql, x, zh, NCTX);

    // 4) out = zh @ Wovh^T (1-pass) -> fp32 output
    tgemm1<0, false><<<dim3(DMODEL / BN, NCTX / BM), 256, SMEM1>>>(
        zh, wvh, out, nullptr, DMODEL, DMODEL, DMODEL, DMODEL);
}